// round 3
// baseline (speedup 1.0000x reference)
#include <cuda_runtime.h>
#include <cuda_fp16.h>

#define N_HID 64
#define MAXN 100000
#define MAXE 3200000
#define NGRAPH 512
#define SCAN_BLK 1024
#define MAXPART 128

// Scratch (device globals — no allocation allowed)
__device__ __align__(16) float  g_dinv[MAXN];
__device__ __align__(16) int    g_cnt2[MAXN];
__device__ __align__(16) int    g_off[MAXN + 1];
__device__ __align__(16) int    g_cur[MAXN];
__device__ __align__(16) int    g_part[MAXPART];
__device__ __align__(16) int2   g_elist[MAXE];          // (src, w-bits fp32)
__device__ __align__(16) __half g_A16[(size_t)MAXN * N_HID];  // fp16 gather input
__device__ __align__(16) float  g_B[(size_t)MAXN * N_HID];    // fp32 aggregated
__device__ __align__(16) float  g_pool[NGRAPH * N_HID];
__device__ float g_cnt[NGRAPH];

// ---------------- histogram of dst (int4-vectorized) ----------------
__global__ void k_zero_cnt(int n) {
    int i = blockIdx.x * blockDim.x + threadIdx.x;
    if (i < n) g_cnt2[i] = 0;
}

__global__ void k_hist(const int* __restrict__ dst, int E) {
    int e4 = (blockIdx.x * blockDim.x + threadIdx.x) * 4;
    if (e4 + 3 < E) {
        int4 d = *(const int4*)(dst + e4);
        atomicAdd(&g_cnt2[d.x], 1);
        atomicAdd(&g_cnt2[d.y], 1);
        atomicAdd(&g_cnt2[d.z], 1);
        atomicAdd(&g_cnt2[d.w], 1);
    } else {
        for (int e = e4; e < E; e++) atomicAdd(&g_cnt2[dst[e]], 1);
    }
}

// ---------------- exclusive scan (3 kernels) ----------------
__global__ void __launch_bounds__(256) k_scan1(int n) {
    __shared__ int wt[8];
    __shared__ int wtex[8];
    const int t = threadIdx.x, lane = t & 31, warp = t >> 5;
    const int base = blockIdx.x * SCAN_BLK + t * 4;
    int a0 = (base + 0 < n) ? g_cnt2[base + 0] : 0;
    int a1 = (base + 1 < n) ? g_cnt2[base + 1] : 0;
    int a2 = (base + 2 < n) ? g_cnt2[base + 2] : 0;
    int a3 = (base + 3 < n) ? g_cnt2[base + 3] : 0;
    int sum4 = a0 + a1 + a2 + a3;
    int v = sum4;
#pragma unroll
    for (int o = 1; o < 32; o <<= 1) {
        int u = __shfl_up_sync(0xFFFFFFFFu, v, o);
        if (lane >= o) v += u;
    }
    if (lane == 31) wt[warp] = v;
    __syncthreads();
    if (t == 0) {
        int run = 0;
#pragma unroll
        for (int w = 0; w < 8; w++) { wtex[w] = run; run += wt[w]; }
        g_part[blockIdx.x] = run;
    }
    __syncthreads();
    int ex = v - sum4 + wtex[warp];
    if (base + 0 < n) g_off[base + 0] = ex;
    if (base + 1 < n) g_off[base + 1] = ex + a0;
    if (base + 2 < n) g_off[base + 2] = ex + a0 + a1;
    if (base + 3 < n) g_off[base + 3] = ex + a0 + a1 + a2;
}

__global__ void k_scan2(int nb) {
    // parallel exclusive scan over <=128 partials, 1 block of 128
    __shared__ int s[MAXPART];
    int t = threadIdx.x;
    int v = (t < nb) ? g_part[t] : 0;
    s[t] = v;
    __syncthreads();
#pragma unroll
    for (int o = 1; o < MAXPART; o <<= 1) {
        int u = (t >= o) ? s[t - o] : 0;
        __syncthreads();
        s[t] += u;
        __syncthreads();
    }
    if (t < nb) g_part[t] = s[t] - v;  // exclusive
}

// scan finalize + dinv + cursor reset (fused)
__global__ void k_scan3(int n, int E) {
    int i = blockIdx.x * blockDim.x + threadIdx.x;
    if (i < n) {
        g_off[i] += g_part[i >> 10];
        g_dinv[i] = rsqrtf((float)g_cnt2[i] + 1.0f);
        g_cur[i] = 0;
    }
    if (i == 0) g_off[n] = E;
}

// ---------------- counting-sort edges by dst, fusing w computation ----------------
__global__ void k_sortscatter(const int* __restrict__ src, const int* __restrict__ dst, int E) {
    int e4 = (blockIdx.x * blockDim.x + threadIdx.x) * 4;
    if (e4 + 3 < E) {
        int4 s = *(const int4*)(src + e4);
        int4 d = *(const int4*)(dst + e4);
        {
            float w = g_dinv[s.x] * g_dinv[d.x];
            int r = atomicAdd(&g_cur[d.x], 1);
            g_elist[g_off[d.x] + r] = make_int2(s.x, __float_as_int(w));
        }
        {
            float w = g_dinv[s.y] * g_dinv[d.y];
            int r = atomicAdd(&g_cur[d.y], 1);
            g_elist[g_off[d.y] + r] = make_int2(s.y, __float_as_int(w));
        }
        {
            float w = g_dinv[s.z] * g_dinv[d.z];
            int r = atomicAdd(&g_cur[d.z], 1);
            g_elist[g_off[d.z] + r] = make_int2(s.z, __float_as_int(w));
        }
        {
            float w = g_dinv[s.w] * g_dinv[d.w];
            int r = atomicAdd(&g_cur[d.w], 1);
            g_elist[g_off[d.w] + r] = make_int2(s.w, __float_as_int(w));
        }
    } else {
        for (int e = e4; e < E; e++) {
            int s = src[e], d = dst[e];
            float w = g_dinv[s] * g_dinv[d];
            int r = atomicAdd(&g_cur[d], 1);
            g_elist[g_off[d] + r] = make_int2(s, __float_as_int(w));
        }
    }
}

// ---------------- GEMM: H16[n][64] = act(X[n][K]) @ W[K][64], output fp16 ----------------
template <int K, bool PRE>
__global__ void __launch_bounds__(256) k_gemm(const float* __restrict__ X,
                                              const float* __restrict__ W,
                                              const float* __restrict__ pb,
                                              __half* __restrict__ H, int n) {
    __shared__ float Ws[64][64];
    __shared__ float Xs[64][64];
    const int row0 = blockIdx.x * 64;
    const int tx = threadIdx.x & 15;
    const int ty = threadIdx.x >> 4;
    float acc[4][4] = {};

    for (int k0 = 0; k0 < K; k0 += 64) {
        for (int i = threadIdx.x; i < 64 * 64; i += 256) {
            int k = i >> 6, c = i & 63;
            Ws[k][c] = W[(size_t)(k0 + k) * 64 + c];
        }
        for (int i = threadIdx.x; i < 64 * 64; i += 256) {
            int r = i >> 6, k = i & 63;
            int row = row0 + r;
            float v = 0.0f;
            if (row < n) {
                v = X[(size_t)row * K + k0 + k];
                if (PRE) v = fmaxf(v + pb[k0 + k], 0.0f);
            }
            Xs[r][k] = v;
        }
        __syncthreads();
#pragma unroll
        for (int k = 0; k < 64; k++) {
            float4 wv = *(const float4*)&Ws[k][tx * 4];
            float x0 = Xs[ty * 4 + 0][k];
            float x1 = Xs[ty * 4 + 1][k];
            float x2 = Xs[ty * 4 + 2][k];
            float x3 = Xs[ty * 4 + 3][k];
            acc[0][0] += x0 * wv.x; acc[0][1] += x0 * wv.y; acc[0][2] += x0 * wv.z; acc[0][3] += x0 * wv.w;
            acc[1][0] += x1 * wv.x; acc[1][1] += x1 * wv.y; acc[1][2] += x1 * wv.z; acc[1][3] += x1 * wv.w;
            acc[2][0] += x2 * wv.x; acc[2][1] += x2 * wv.y; acc[2][2] += x2 * wv.z; acc[2][3] += x2 * wv.w;
            acc[3][0] += x3 * wv.x; acc[3][1] += x3 * wv.y; acc[3][2] += x3 * wv.z; acc[3][3] += x3 * wv.w;
        }
        __syncthreads();
    }
#pragma unroll
    for (int i = 0; i < 4; i++) {
        int row = row0 + ty * 4 + i;
        if (row < n) {
            union { uint2 u; __half2 h[2]; } pk;
            pk.h[0] = __floats2half2_rn(acc[i][0], acc[i][1]);
            pk.h[1] = __floats2half2_rn(acc[i][2], acc[i][3]);
            *(uint2*)&H[(size_t)row * 64 + tx * 4] = pk.u;
        }
    }
}

// ---------------- gather-only aggregation: warp per dst node, fp16 input ----------------
__global__ void __launch_bounds__(256) k_gather(const __half* __restrict__ Ain,
                                                float* __restrict__ Hout, int n) {
    int wid = (blockIdx.x * blockDim.x + threadIdx.x) >> 5;
    if (wid >= n) return;
    const int lane = threadIdx.x & 31;
    const int beg = g_off[wid];
    const int end = g_off[wid + 1];
    const __half2* A = (const __half2*)Ain;

    float dv = g_dinv[wid];
    float2 a = __half22float2(A[(size_t)wid * 32 + lane]);
    float2 acc = make_float2(a.x * dv * dv, a.y * dv * dv);

    int j = beg;
    for (; j + 4 <= end; j += 4) {
        int2 p0 = g_elist[j + 0];
        int2 p1 = g_elist[j + 1];
        int2 p2 = g_elist[j + 2];
        int2 p3 = g_elist[j + 3];
        float2 v0 = __half22float2(A[(size_t)p0.x * 32 + lane]);
        float2 v1 = __half22float2(A[(size_t)p1.x * 32 + lane]);
        float2 v2 = __half22float2(A[(size_t)p2.x * 32 + lane]);
        float2 v3 = __half22float2(A[(size_t)p3.x * 32 + lane]);
        float w0 = __int_as_float(p0.y), w1 = __int_as_float(p1.y);
        float w2 = __int_as_float(p2.y), w3 = __int_as_float(p3.y);
        acc.x += w0 * v0.x; acc.y += w0 * v0.y;
        acc.x += w1 * v1.x; acc.y += w1 * v1.y;
        acc.x += w2 * v2.x; acc.y += w2 * v2.y;
        acc.x += w3 * v3.x; acc.y += w3 * v3.y;
    }
    for (; j < end; j++) {
        int2 p = g_elist[j];
        float2 v = __half22float2(A[(size_t)p.x * 32 + lane]);
        float w = __int_as_float(p.y);
        acc.x += w * v.x; acc.y += w * v.y;
    }
    *(float2*)(Hout + (size_t)wid * 64 + lane * 2) = acc;
}

// ---------------- pooling ----------------
__device__ __forceinline__ void red_add_v4(float* p, float a, float b, float c, float d) {
    unsigned long long gp;
    asm("cvta.to.global.u64 %0, %1;" : "=l"(gp) : "l"(p));
    asm volatile("red.global.add.v4.f32 [%0], {%1, %2, %3, %4};"
                 :: "l"(gp), "f"(a), "f"(b), "f"(c), "f"(d) : "memory");
}

__global__ void k_zero_pool() {
    int i = blockIdx.x * blockDim.x + threadIdx.x;
    if (i < NGRAPH * N_HID) g_pool[i] = 0.0f;
    if (i < NGRAPH) g_cnt[i] = 0.0f;
}

__global__ void k_pool(const float* __restrict__ H, const float* __restrict__ b3,
                       const int* __restrict__ batch, int n) {
    int idx = blockIdx.x * blockDim.x + threadIdx.x;
    int i = idx >> 4, c = idx & 15;
    if (i >= n) return;
    int g = batch[i];
    float4 h = *(const float4*)&H[(size_t)i * 64 + c * 4];
    float4 bb = *(const float4*)&b3[c * 4];
    h.x = fmaxf(h.x + bb.x, 0.0f);
    h.y = fmaxf(h.y + bb.y, 0.0f);
    h.z = fmaxf(h.z + bb.z, 0.0f);
    h.w = fmaxf(h.w + bb.w, 0.0f);
    red_add_v4(&g_pool[g * 64 + c * 4], h.x, h.y, h.z, h.w);
    if (c == 0) atomicAdd(&g_cnt[g], 1.0f);
}

// ---------------- classifier head ----------------
__global__ void k_classifier(const float* __restrict__ Wc1, const float* __restrict__ bc1,
                             const float* __restrict__ Wc2, const float* __restrict__ bc2,
                             float* __restrict__ out) {
    __shared__ float p[64];
    __shared__ float z[32];
    int g = blockIdx.x;
    int t = threadIdx.x;  // 32 threads
    float inv = 1.0f / fmaxf(g_cnt[g], 1.0f);
    p[t] = g_pool[g * 64 + t] * inv;
    p[t + 32] = g_pool[g * 64 + 32 + t] * inv;
    __syncwarp();
    float acc = bc1[t];
#pragma unroll
    for (int k = 0; k < 64; k++) acc += p[k] * Wc1[k * 32 + t];
    z[t] = fmaxf(acc, 0.0f);
    __syncwarp();
    if (t < 10) {
        float a = bc2[t];
#pragma unroll
        for (int k = 0; k < 32; k++) a += z[k] * Wc2[k * 10 + t];
        out[g * 10 + t] = a;
    }
}

extern "C" void kernel_launch(void* const* d_in, const int* in_sizes, int n_in,
                              void* d_out, int out_size) {
    const float* x    = (const float*)d_in[0];
    const int*   ei   = (const int*)d_in[1];
    const int*   bat  = (const int*)d_in[2];
    const float* W1   = (const float*)d_in[3];
    const float* b1   = (const float*)d_in[4];
    const float* W2   = (const float*)d_in[5];
    const float* b2   = (const float*)d_in[6];
    const float* W3   = (const float*)d_in[7];
    const float* b3   = (const float*)d_in[8];
    const float* Wc1  = (const float*)d_in[9];
    const float* bc1  = (const float*)d_in[10];
    const float* Wc2  = (const float*)d_in[11];
    const float* bc2  = (const float*)d_in[12];

    const int n = in_sizes[0] / 128;
    const int E = in_sizes[1] / 2;
    const int* src = ei;
    const int* dst = ei + E;

    __half* dA;
    float*  dB;
    cudaGetSymbolAddress((void**)&dA, g_A16);
    cudaGetSymbolAddress((void**)&dB, g_B);

    const int TB = 256;
    int gn   = (n + TB - 1) / TB;
    int gE4  = (E + 4 * TB - 1) / (4 * TB);
    int gn16 = (int)(((long long)n * 16 + TB - 1) / TB);
    int gW   = (int)(((long long)n * 32 + TB - 1) / TB);
    int gRow = (n + 63) / 64;
    int nb   = (n + SCAN_BLK - 1) / SCAN_BLK;

    // ---- build CSR by dst + norms (once per call, reused by all 3 layers) ----
    k_zero_cnt<<<gn, TB>>>(n);
    k_hist<<<gE4, TB>>>(dst, E);
    k_scan1<<<nb, 256>>>(n);
    k_scan2<<<1, MAXPART>>>(nb);
    k_scan3<<<gn, TB>>>(n, E);
    k_sortscatter<<<gE4, TB>>>(src, dst, E);

    // layer 1: A16 = x @ W1 ; B = aggregate(A16)
    k_gemm<128, false><<<gRow, TB>>>(x, W1, nullptr, dA, n);
    k_gather<<<gW, TB>>>(dA, dB, n);

    // layer 2
    k_gemm<64, true><<<gRow, TB>>>(dB, W2, b1, dA, n);
    k_gather<<<gW, TB>>>(dA, dB, n);

    // layer 3
    k_gemm<64, true><<<gRow, TB>>>(dB, W3, b2, dA, n);
    k_gather<<<gW, TB>>>(dA, dB, n);

    // mean-pool (fuses relu(B + b3)) + classifier
    k_zero_pool<<<(NGRAPH * N_HID + TB - 1) / TB, TB>>>();
    k_pool<<<gn16, TB>>>(dB, b3, bat, n);
    k_classifier<<<NGRAPH, 32>>>(Wc1, bc1, Wc2, bc2, (float*)d_out);
}